// round 14
// baseline (speedup 1.0000x reference)
#include <cuda_runtime.h>
#include <math.h>

#define S_  1024
#define B_  128
#define F_  202
#define H_  100
#define K_  19
#define N2_ 200   // 2*H

// ---- scratch (device globals: no runtime allocation allowed) ----
__device__ float g_xp[(size_t)S_ * B_ * N2_];  // input projections, both dirs
__device__ float g_h [(size_t)S_ * B_ * N2_];  // hidden states [hf | hb]
__device__ float g_em[(size_t)S_ * B_ * K_];   // softmax emissions

// ---- packed dual-fp32 helpers (sm_103a f32x2 pipe) ----
static __device__ __forceinline__ unsigned long long ffma2_(
    unsigned long long a, unsigned long long b, unsigned long long c)
{
    unsigned long long d;
    asm("fma.rn.f32x2 %0, %1, %2, %3;" : "=l"(d) : "l"(a), "l"(b), "l"(c));
    return d;
}
static __device__ __forceinline__ unsigned long long addf2_(
    unsigned long long a, unsigned long long b)
{
    unsigned long long d;
    asm("add.rn.f32x2 %0, %1, %2;" : "=l"(d) : "l"(a), "l"(b));
    return d;
}
static __device__ __forceinline__ float lo_(unsigned long long v) {
    return __uint_as_float((unsigned)(v & 0xffffffffull));
}
static __device__ __forceinline__ float hi_(unsigned long long v) {
    return __uint_as_float((unsigned)(v >> 32));
}
static __device__ __forceinline__ unsigned long long pack2_(float lo, float hi) {
    unsigned long long r;
    asm("mov.b64 %0, {%1, %2};" : "=l"(r) : "f"(lo), "f"(hi));
    return r;
}
// predicated stores (single @p instruction, no BSSY/BSYNC envelope)
static __device__ __forceinline__ void sts_pred_(int pred, unsigned addr, float v) {
    asm volatile("{ .reg .pred p; setp.ne.s32 p, %0, 0; @p st.shared.f32 [%1], %2; }"
                 :: "r"(pred), "r"(addr), "f"(v));
}
static __device__ __forceinline__ void stg_pred_(int pred, float* ptr, float v) {
    asm volatile("{ .reg .pred p; setp.ne.s32 p, %0, 0; @p st.global.f32 [%1], %2; }"
                 :: "r"(pred), "l"(ptr), "f"(v));
}
static __device__ __forceinline__ unsigned smem_u32_(const void* p) {
    unsigned a;
    asm("{ .reg .u64 t; cvta.to.shared.u64 t, %1; cvt.u32.u64 %0, t; }" : "=r"(a) : "l"(p));
    return a;
}
// ---- mbarrier + 1D bulk-async copy (UBLKCP) ----
static __device__ __forceinline__ void mbar_init_(unsigned mbar, int cnt) {
    asm volatile("mbarrier.init.shared.b64 [%0], %1;" :: "r"(mbar), "r"(cnt) : "memory");
}
static __device__ __forceinline__ void mbar_expect_(unsigned mbar, unsigned bytes) {
    asm volatile("mbarrier.arrive.expect_tx.shared.b64 _, [%0], %1;"
                 :: "r"(mbar), "r"(bytes) : "memory");
}
static __device__ __forceinline__ void bulk_g2s_(unsigned dst, const void* src,
                                                 unsigned bytes, unsigned mbar) {
    asm volatile("cp.async.bulk.shared::cta.global.mbarrier::complete_tx::bytes "
                 "[%0], [%1], %2, [%3];"
                 :: "r"(dst), "l"(src), "r"(bytes), "r"(mbar) : "memory");
}
static __device__ __forceinline__ void mbar_wait_(unsigned mbar, unsigned phase) {
    unsigned done;
    asm volatile(
        "{\n\t.reg .pred p;\n\t"
        "mbarrier.try_wait.parity.acquire.cta.shared::cta.b64 p, [%1], %2;\n\t"
        "selp.b32 %0, 1, 0, p;\n\t}"
        : "=r"(done) : "r"(mbar), "r"(phase) : "memory");
    if (!done) {
        asm volatile(
            "{\n\t.reg .pred P1;\n\t"
            "WL_%=:\n\t"
            "mbarrier.try_wait.parity.acquire.cta.shared::cta.b64 P1, [%0], %1, 0x989680;\n\t"
            "@P1 bra.uni WD_%=;\n\t"
            "bra.uni WL_%=;\n\t"
            "WD_%=:\n\t}"
            :: "r"(mbar), "r"(phase) : "memory");
    }
}

// profiling-slot spacer (ncu captures the 4th app launch; make it rnn)
__global__ void noop_kernel() {}

// =====================================================================
// Kernel 1: persistent input projection (proven R10/R12 config).
// =====================================================================
#define PG_DIR  74
#define PG_G    148
#define PJ_T    640
#define TILE_BYTES 51712u                 // 64*202*4
#define OFF_A0  0
#define OFF_A1  12936
#define OFF_B   25872                     // 100*204
#define OFF_EP  46272                     // 64*101
#define OFF_MB  52736
#define PJ_SMEM ((OFF_MB + 8) * 4)        // 210976 bytes
#define NTILES  2048

__global__ __launch_bounds__(PJ_T, 1) void proj_kernel(
    const float* __restrict__ x,
    const float* __restrict__ Wf, const float* __restrict__ Wb,
    const float* __restrict__ bihf, const float* __restrict__ bhhf,
    const float* __restrict__ bihb, const float* __restrict__ bhhb)
{
    extern __shared__ __align__(16) float smf[];
    const int tid = threadIdx.x;
    const int dir = (blockIdx.x >= PG_DIR) ? 1 : 0;
    const int cid = blockIdx.x - dir * PG_DIR;   // 0..73
    const float* W   = dir ? Wb   : Wf;
    const float* bih = dir ? bihb : bihf;
    const float* bhh = dir ? bhhb : bhhf;

    const unsigned mb0 = smem_u32_(smf + OFF_MB);
    const unsigned mb1 = mb0 + 8;
    const unsigned ab0 = smem_u32_(smf + OFF_A0);
    const unsigned ab1 = smem_u32_(smf + OFF_A1);

    if (tid == 0) { mbar_init_(mb0, 1); mbar_init_(mb1, 1); }
    if (tid < 8)       smf[OFF_A0 + 12928 + tid] = 0.f;
    else if (tid < 16) smf[OFF_A1 + 12928 + (tid - 8)] = 0.f;

    for (int e = tid; e < 100 * 204; e += PJ_T) {
        int n = e / 204, f = e - n * 204;
        smf[OFF_B + e] = (f < F_) ? W[n * F_ + f] : 0.f;
    }
    __syncthreads();

    if (tid == 0) {
        mbar_expect_(mb0, TILE_BYTES);
        bulk_g2s_(ab0, x + (size_t)cid * 12928, TILE_BYTES, mb0);
    }

    const int tx = tid & 31;
    const int w  = tid >> 5;
    float bias_j[5];
    #pragma unroll
    for (int j = 0; j < 5; j++) { int c = w + 20 * j; bias_j[j] = bih[c] + bhh[c]; }

    const ulonglong2* B2 = (const ulonglong2*)(smf + OFF_B);
    float* ep = smf + OFF_EP;

    int cur = 0;
    unsigned ph0 = 0, ph1 = 0;
    for (int mt = cid; mt < NTILES; mt += PG_DIR) {
        int nt = mt + PG_DIR;
        if (tid == 0 && nt < NTILES) {
            unsigned mbn = cur ? mb0 : mb1;
            unsigned abn = cur ? ab0 : ab1;
            mbar_expect_(mbn, TILE_BYTES);
            bulk_g2s_(abn, x + (size_t)nt * 12928, TILE_BYTES, mbn);
        }
        if (cur == 0) { mbar_wait_(mb0, ph0); }
        else          { mbar_wait_(mb1, ph1); }

        const unsigned long long* A8 =
            (const unsigned long long*)(smf + (cur ? OFF_A1 : OFF_A0));
        const int rb0 = 101 * tx;
        const int rb1 = 101 * (tx + 32);

        unsigned long long acc2[2][5];
        #pragma unroll
        for (int i = 0; i < 2; i++)
            #pragma unroll
            for (int j = 0; j < 5; j++) acc2[i][j] = 0ull;

        #pragma unroll 3
        for (int kk = 0; kk < 51; kk++) {
            unsigned long long a00 = A8[rb0 + 2 * kk];
            unsigned long long a01 = A8[rb0 + 2 * kk + 1];
            unsigned long long a10 = A8[rb1 + 2 * kk];
            unsigned long long a11 = A8[rb1 + 2 * kk + 1];
            ulonglong2 b[5];
            #pragma unroll
            for (int j = 0; j < 5; j++) b[j] = B2[(w + 20 * j) * 51 + kk];
            #pragma unroll
            for (int j = 0; j < 5; j++) {
                acc2[0][j] = ffma2_(a00, b[j].x, acc2[0][j]);
                acc2[0][j] = ffma2_(a01, b[j].y, acc2[0][j]);
                acc2[1][j] = ffma2_(a10, b[j].x, acc2[1][j]);
                acc2[1][j] = ffma2_(a11, b[j].y, acc2[1][j]);
            }
        }
        if (cur == 0) ph0 ^= 1; else ph1 ^= 1;

        #pragma unroll
        for (int j = 0; j < 5; j++) {
            int c = w + 20 * j;
            ep[tx * 101 + c]        = lo_(acc2[0][j]) + hi_(acc2[0][j]) + bias_j[j];
            ep[(tx + 32) * 101 + c] = lo_(acc2[1][j]) + hi_(acc2[1][j]) + bias_j[j];
        }
        __syncthreads();
        {
            float* gout = g_xp + (size_t)(mt * 64) * N2_ + dir * H_;
            #pragma unroll
            for (int q = 0; q < 10; q++) {
                int e = tid + q * PJ_T;
                int r = e / 100, c = e - r * 100;
                gout[(size_t)r * N2_ + c] = ep[r * 101 + c];
            }
        }
        __syncthreads();
        cur ^= 1;
    }
}

// =====================================================================
// Kernel 2: recurrent scans, PAIRED-CHAIN design.
//   CTA c (0..127) processes chains (dir, b) and (dir, b+64), dir=c>>6,
//   b=c&63 -- SAME dir => SAME Whh (weights once, 100 regs, no spill).
//   Each thread interleaves both chains' dot products in one warp:
//   chain B's instructions fill chain A's latency bubbles. grid 128 =
//   1 CTA/SM, 1 warp/SMSP. One barrier per step covers both chains.
// =====================================================================
__global__ __launch_bounds__(128, 1) void rnn_kernel(
    const float* __restrict__ Whhf, const float* __restrict__ Whhb)
{
    const int c   = blockIdx.x;          // 0..127
    const int dir = c >> 6;
    const int b0  = c & 63;              // chain A batch
    const int b1  = b0 + 64;             // chain B batch
    const int j   = threadIdx.x;         // 0..127
    const int jc  = (j < H_) ? j : (H_ - 1);
    const int act = (j < H_) ? 1 : 0;

    __shared__ __align__(16) float hs[2][2][104];   // [chain][phase][h]

    const float* Whh = dir ? Whhb : Whhf;
    unsigned long long w2[50];
    {
        const ulonglong2* wp = (const ulonglong2*)(Whh + jc * H_);
        #pragma unroll
        for (int k = 0; k < 25; k++) { ulonglong2 t = wp[k]; w2[2*k] = t.x; w2[2*k+1] = t.y; }
    }
    if (j < 104) {
        hs[0][0][j] = 0.f; hs[0][1][j] = 0.f;
        hs[1][0][j] = 0.f; hs[1][1][j] = 0.f;
    }
    __syncthreads();

    const unsigned hbA = smem_u32_(&hs[0][0][0]);
    const unsigned hbB = smem_u32_(&hs[1][0][0]);
    const float* xpA = g_xp + (size_t)b0 * N2_ + dir * H_ + jc;
    const float* xpB = g_xp + (size_t)b1 * N2_ + dir * H_ + jc;
    float*       hgA = g_h  + (size_t)b0 * N2_ + dir * H_ + jc;
    float*       hgB = g_h  + (size_t)b1 * N2_ + dir * H_ + jc;
    const int s0 = dir ? (S_ - 1) : 0;
    const int ds = dir ? -1 : 1;
    const int STRIDE = B_ * N2_;  // 25600

    float xqA[2], xqB[2];
    #pragma unroll
    for (int q = 0; q < 2; q++) {
        xqA[q] = xpA[(size_t)(s0 + ds * q) * STRIDE];
        xqB[q] = xpB[(size_t)(s0 + ds * q) * STRIDE];
    }

    int p = 0;
    #pragma unroll 2
    for (int t = 0; t < S_; t++) {
        const int s = s0 + ds * t;
        const float xA = xqA[t & 1];
        const float xB = xqB[t & 1];
        int tp = t + 2; tp = (tp < S_) ? tp : (S_ - 1);     // clamp, branch-free
        xqA[t & 1] = xpA[(size_t)(s0 + ds * tp) * STRIDE];
        xqB[t & 1] = xpB[(size_t)(s0 + ds * tp) * STRIDE];

        unsigned long long aA[4], aB[4];
        aA[0] = pack2_(xA, 0.f); aB[0] = pack2_(xB, 0.f);
        #pragma unroll
        for (int q = 1; q < 4; q++) { aA[q] = 0ull; aB[q] = 0ull; }

        const ulonglong2* hvA = (const ulonglong2*)(hs[0][p]);
        const ulonglong2* hvB = (const ulonglong2*)(hs[1][p]);
        #pragma unroll
        for (int k = 0; k < 25; k++) {
            ulonglong2 h2A = hvA[k];
            ulonglong2 h2B = hvB[k];
            aA[(2*k)     & 3] = ffma2_(w2[2*k],     h2A.x, aA[(2*k)     & 3]);
            aB[(2*k)     & 3] = ffma2_(w2[2*k],     h2B.x, aB[(2*k)     & 3]);
            aA[(2*k + 1) & 3] = ffma2_(w2[2*k + 1], h2A.y, aA[(2*k + 1) & 3]);
            aB[(2*k + 1) & 3] = ffma2_(w2[2*k + 1], h2B.y, aB[(2*k + 1) & 3]);
        }
        unsigned long long rA = addf2_(addf2_(aA[0], aA[2]), addf2_(aA[1], aA[3]));
        unsigned long long rB = addf2_(addf2_(aB[0], aB[2]), addf2_(aB[1], aB[3]));
        float accA = lo_(rA) + hi_(rA);
        float accB = lo_(rB) + hi_(rB);

        // tanh(x) = 1 - 2/(e^{2x}+1); inf-safe, ~1e-7 abs err
        float eA = __expf(accA + accA);
        float eB = __expf(accB + accB);
        float hA = 1.f - __fdividef(2.f, eA + 1.f);
        float hB = 1.f - __fdividef(2.f, eB + 1.f);

        sts_pred_(act, hbA + (unsigned)((p ^ 1) * 104 + j) * 4u, hA);
        sts_pred_(act, hbB + (unsigned)((p ^ 1) * 104 + j) * 4u, hB);
        stg_pred_(act, hgA + (size_t)s * STRIDE, hA);
        stg_pred_(act, hgB + (size_t)s * STRIDE, hB);
        __syncthreads();
        p ^= 1;
    }
}

// =====================================================================
// Kernel 3: logits + softmax -> emissions. Thread per (s,b) row.
// =====================================================================
__global__ __launch_bounds__(256) void logits_kernel(
    const float* __restrict__ Wout, const float* __restrict__ bout)
{
    __shared__ __align__(16) float wt[N2_ * 20];   // W_out^T, K padded 19->20
    const int tid = threadIdx.x;
    for (int e = tid; e < N2_ * 20; e += 256) {
        int f = e / 20, k = e - f * 20;
        wt[e] = (k < K_) ? Wout[k * N2_ + f] : 0.f;
    }
    __syncthreads();

    const int m = blockIdx.x * 256 + tid;
    const float4* hp = (const float4*)(g_h + (size_t)m * N2_);
    const ulonglong2* wt2 = (const ulonglong2*)wt;

    unsigned long long acc2[10];
    #pragma unroll
    for (int q = 0; q < 10; q++) acc2[q] = 0ull;

    for (int f4 = 0; f4 < 50; f4++) {
        float4 hv = __ldg(&hp[f4]);
        float hh[4] = {hv.x, hv.y, hv.z, hv.w};
        #pragma unroll
        for (int cc = 0; cc < 4; cc++) {
            const int f = f4 * 4 + cc;
            const unsigned long long hb = pack2_(hh[cc], hh[cc]);
            #pragma unroll
            for (int q = 0; q < 5; q++) {
                ulonglong2 wv = wt2[f * 5 + q];
                acc2[2*q]     = ffma2_(hb, wv.x, acc2[2*q]);
                acc2[2*q + 1] = ffma2_(hb, wv.y, acc2[2*q + 1]);
            }
        }
    }

    float acc[20];
    #pragma unroll
    for (int q = 0; q < 10; q++) { acc[2*q] = lo_(acc2[q]); acc[2*q+1] = hi_(acc2[q]); }

    float mx = -1e30f;
    #pragma unroll
    for (int k = 0; k < K_; k++) { acc[k] += __ldg(&bout[k]); mx = fmaxf(mx, acc[k]); }
    float sum = 0.f;
    #pragma unroll
    for (int k = 0; k < K_; k++) { acc[k] = __expf(acc[k] - mx); sum += acc[k]; }
    const float inv = 1.f / sum;
    float* e = g_em + (size_t)m * K_;
    #pragma unroll
    for (int k = 0; k < K_; k++) e[k] = acc[k] * inv;
}

// =====================================================================
// Kernel 4: Viterbi decode. Warp per sequence; smem score exchange.
// =====================================================================
__global__ __launch_bounds__(256) void viterbi_kernel(
    const float* __restrict__ start, const float* __restrict__ endt,
    const float* __restrict__ trans, float* __restrict__ out)
{
    __shared__ unsigned char hist[8][127][20];
    __shared__ __align__(16) float sc[8][2][20];
    const int w    = threadIdx.x >> 5;
    const int lane = threadIdx.x & 31;
    const int n    = blockIdx.x * 8 + w;
    const int j    = lane;
    const bool act = (j < K_);

    float tr[K_];
    #pragma unroll
    for (int i = 0; i < K_; i++) tr[i] = act ? trans[i * K_ + j] : 0.f;

    const float* emn = g_em + (size_t)n * B_ * K_;
    float score = act ? (start[j] + emn[j]) : -1e30f;
    if (act) sc[w][0][j] = score;
    if (lane == 19) sc[w][0][19] = -1e30f;
    __syncwarp();

    int p = 0;
    for (int t = 1; t < B_; t++) {
        const float e = act ? emn[t * K_ + j] : 0.f;
        float4 s0 = *(const float4*)&sc[w][p][0];
        float4 s1 = *(const float4*)&sc[w][p][4];
        float4 s2 = *(const float4*)&sc[w][p][8];
        float4 s3 = *(const float4*)&sc[w][p][12];
        float4 s4 = *(const float4*)&sc[w][p][16];
        float s[20] = {s0.x,s0.y,s0.z,s0.w, s1.x,s1.y,s1.z,s1.w,
                       s2.x,s2.y,s2.z,s2.w, s3.x,s3.y,s3.z,s3.w,
                       s4.x,s4.y,s4.z,s4.w};
        float bv[K_]; int bi[K_];
        #pragma unroll
        for (int i = 0; i < K_; i++) { bv[i] = s[i] + tr[i]; bi[i] = i; }
        // tie-stable tree argmax: strict > keeps the LOWER index on ties
        #pragma unroll
        for (int st = 1; st < 32; st <<= 1)
            #pragma unroll
            for (int i = 0; i + st < K_; i += 2 * st) {
                bool take = (bv[i + st] > bv[i]);
                bv[i] = take ? bv[i + st] : bv[i];
                bi[i] = take ? bi[i + st] : bi[i];
            }
        if (act) hist[w][t - 1][j] = (unsigned char)bi[0];
        score = bv[0] + e;
        if (act) sc[w][p ^ 1][j] = score;
        __syncwarp();
        p ^= 1;
    }

    float v  = act ? (score + endt[j]) : -1e30f;
    int  idx = j;
    #pragma unroll
    for (int off = 16; off; off >>= 1) {
        float ov = __shfl_down_sync(0xffffffffu, v, off);
        int   oi = __shfl_down_sync(0xffffffffu, idx, off);
        if (ov > v || (ov == v && oi < idx)) { v = ov; idx = oi; }
    }
    __syncwarp();

    if (lane == 0) {
        int tag = idx;
        float* o = out + (size_t)n * B_;
        o[B_ - 1] = (float)tag;
        for (int t = B_ - 2; t >= 0; t--) {
            tag  = hist[w][t][tag];
            o[t] = (float)tag;
        }
    }
}

// =====================================================================
extern "C" void kernel_launch(void* const* d_in, const int* in_sizes, int n_in,
                              void* d_out, int out_size)
{
    const float* x     = (const float*)d_in[0];
    const float* Wihf  = (const float*)d_in[1];
    const float* Whhf  = (const float*)d_in[2];
    const float* bihf  = (const float*)d_in[3];
    const float* bhhf  = (const float*)d_in[4];
    const float* Wihb  = (const float*)d_in[5];
    const float* Whhb  = (const float*)d_in[6];
    const float* bihb  = (const float*)d_in[7];
    const float* bhhb  = (const float*)d_in[8];
    const float* Wout  = (const float*)d_in[9];
    const float* bout  = (const float*)d_in[10];
    const float* start = (const float*)d_in[11];
    const float* endt  = (const float*)d_in[12];
    const float* trans = (const float*)d_in[13];
    float* out = (float*)d_out;

    cudaFuncSetAttribute(proj_kernel, cudaFuncAttributeMaxDynamicSharedMemorySize, PJ_SMEM);

    // spacers: put rnn_kernel in the ncu capture slot (4th app launch)
    noop_kernel<<<1, 32>>>();
    noop_kernel<<<1, 32>>>();
    proj_kernel<<<PG_G, PJ_T, PJ_SMEM>>>(x, Wihf, Wihb, bihf, bhhf, bihb, bhhb);
    rnn_kernel<<<B_, 128>>>(Whhf, Whhb);
    logits_kernel<<<(S_ * B_) / 256, 256>>>(Wout, bout);
    viterbi_kernel<<<S_ / 8, 256>>>(start, endt, trans, out);
}

// round 15
// speedup vs baseline: 1.0876x; 1.0876x over previous
#include <cuda_runtime.h>
#include <math.h>

#define S_  1024
#define B_  128
#define F_  202
#define H_  100
#define K_  19
#define N2_ 200   // 2*H

// ---- scratch (device globals: no runtime allocation allowed) ----
__device__ float g_xp[(size_t)S_ * B_ * N2_];  // input projections, both dirs
__device__ float g_h [(size_t)S_ * B_ * N2_];  // hidden states [hf | hb]
__device__ float g_em[(size_t)S_ * B_ * K_];   // softmax emissions

// ---- packed dual-fp32 helpers (sm_103a f32x2 pipe) ----
static __device__ __forceinline__ unsigned long long ffma2_(
    unsigned long long a, unsigned long long b, unsigned long long c)
{
    unsigned long long d;
    asm("fma.rn.f32x2 %0, %1, %2, %3;" : "=l"(d) : "l"(a), "l"(b), "l"(c));
    return d;
}
static __device__ __forceinline__ unsigned long long addf2_(
    unsigned long long a, unsigned long long b)
{
    unsigned long long d;
    asm("add.rn.f32x2 %0, %1, %2;" : "=l"(d) : "l"(a), "l"(b));
    return d;
}
static __device__ __forceinline__ float lo_(unsigned long long v) {
    return __uint_as_float((unsigned)(v & 0xffffffffull));
}
static __device__ __forceinline__ float hi_(unsigned long long v) {
    return __uint_as_float((unsigned)(v >> 32));
}
static __device__ __forceinline__ unsigned long long pack2_(float lo, float hi) {
    unsigned long long r;
    asm("mov.b64 %0, {%1, %2};" : "=l"(r) : "f"(lo), "f"(hi));
    return r;
}
// predicated stores (single @p instruction, no BSSY/BSYNC envelope)
static __device__ __forceinline__ void sts_pred_(int pred, unsigned addr, float v) {
    asm volatile("{ .reg .pred p; setp.ne.s32 p, %0, 0; @p st.shared.f32 [%1], %2; }"
                 :: "r"(pred), "r"(addr), "f"(v));
}
static __device__ __forceinline__ void stg_pred_(int pred, float* ptr, float v) {
    asm volatile("{ .reg .pred p; setp.ne.s32 p, %0, 0; @p st.global.f32 [%1], %2; }"
                 :: "r"(pred), "l"(ptr), "f"(v));
}
static __device__ __forceinline__ unsigned smem_u32_(const void* p) {
    unsigned a;
    asm("{ .reg .u64 t; cvta.to.shared.u64 t, %1; cvt.u32.u64 %0, t; }" : "=r"(a) : "l"(p));
    return a;
}
// ---- mbarrier + 1D bulk-async copy (UBLKCP) ----
static __device__ __forceinline__ void mbar_init_(unsigned mbar, int cnt) {
    asm volatile("mbarrier.init.shared.b64 [%0], %1;" :: "r"(mbar), "r"(cnt) : "memory");
}
static __device__ __forceinline__ void mbar_expect_(unsigned mbar, unsigned bytes) {
    asm volatile("mbarrier.arrive.expect_tx.shared.b64 _, [%0], %1;"
                 :: "r"(mbar), "r"(bytes) : "memory");
}
static __device__ __forceinline__ void bulk_g2s_(unsigned dst, const void* src,
                                                 unsigned bytes, unsigned mbar) {
    asm volatile("cp.async.bulk.shared::cta.global.mbarrier::complete_tx::bytes "
                 "[%0], [%1], %2, [%3];"
                 :: "r"(dst), "l"(src), "r"(bytes), "r"(mbar) : "memory");
}
static __device__ __forceinline__ void mbar_wait_(unsigned mbar, unsigned phase) {
    unsigned done;
    asm volatile(
        "{\n\t.reg .pred p;\n\t"
        "mbarrier.try_wait.parity.acquire.cta.shared::cta.b64 p, [%1], %2;\n\t"
        "selp.b32 %0, 1, 0, p;\n\t}"
        : "=r"(done) : "r"(mbar), "r"(phase) : "memory");
    if (!done) {
        asm volatile(
            "{\n\t.reg .pred P1;\n\t"
            "WL_%=:\n\t"
            "mbarrier.try_wait.parity.acquire.cta.shared::cta.b64 P1, [%0], %1, 0x989680;\n\t"
            "@P1 bra.uni WD_%=;\n\t"
            "bra.uni WL_%=;\n\t"
            "WD_%=:\n\t}"
            :: "r"(mbar), "r"(phase) : "memory");
    }
}

// =====================================================================
// Kernel 1: persistent input projection (proven R10 config, unchanged).
// =====================================================================
#define PG_DIR  74
#define PG_G    148
#define PJ_T    640
#define TILE_BYTES 51712u                 // 64*202*4
#define OFF_A0  0
#define OFF_A1  12936
#define OFF_B   25872                     // 100*204
#define OFF_EP  46272                     // 64*101
#define OFF_MB  52736
#define PJ_SMEM ((OFF_MB + 8) * 4)        // 210976 bytes
#define NTILES  2048

__global__ __launch_bounds__(PJ_T, 1) void proj_kernel(
    const float* __restrict__ x,
    const float* __restrict__ Wf, const float* __restrict__ Wb,
    const float* __restrict__ bihf, const float* __restrict__ bhhf,
    const float* __restrict__ bihb, const float* __restrict__ bhhb)
{
    extern __shared__ __align__(16) float smf[];
    const int tid = threadIdx.x;
    const int dir = (blockIdx.x >= PG_DIR) ? 1 : 0;
    const int cid = blockIdx.x - dir * PG_DIR;   // 0..73
    const float* W   = dir ? Wb   : Wf;
    const float* bih = dir ? bihb : bihf;
    const float* bhh = dir ? bhhb : bhhf;

    const unsigned mb0 = smem_u32_(smf + OFF_MB);
    const unsigned mb1 = mb0 + 8;
    const unsigned ab0 = smem_u32_(smf + OFF_A0);
    const unsigned ab1 = smem_u32_(smf + OFF_A1);

    if (tid == 0) { mbar_init_(mb0, 1); mbar_init_(mb1, 1); }
    if (tid < 8)       smf[OFF_A0 + 12928 + tid] = 0.f;
    else if (tid < 16) smf[OFF_A1 + 12928 + (tid - 8)] = 0.f;

    for (int e = tid; e < 100 * 204; e += PJ_T) {
        int n = e / 204, f = e - n * 204;
        smf[OFF_B + e] = (f < F_) ? W[n * F_ + f] : 0.f;
    }
    __syncthreads();

    if (tid == 0) {
        mbar_expect_(mb0, TILE_BYTES);
        bulk_g2s_(ab0, x + (size_t)cid * 12928, TILE_BYTES, mb0);
    }

    const int tx = tid & 31;
    const int w  = tid >> 5;
    float bias_j[5];
    #pragma unroll
    for (int j = 0; j < 5; j++) { int c = w + 20 * j; bias_j[j] = bih[c] + bhh[c]; }

    const ulonglong2* B2 = (const ulonglong2*)(smf + OFF_B);
    float* ep = smf + OFF_EP;

    int cur = 0;
    unsigned ph0 = 0, ph1 = 0;
    for (int mt = cid; mt < NTILES; mt += PG_DIR) {
        int nt = mt + PG_DIR;
        if (tid == 0 && nt < NTILES) {
            unsigned mbn = cur ? mb0 : mb1;
            unsigned abn = cur ? ab0 : ab1;
            mbar_expect_(mbn, TILE_BYTES);
            bulk_g2s_(abn, x + (size_t)nt * 12928, TILE_BYTES, mbn);
        }
        if (cur == 0) { mbar_wait_(mb0, ph0); }
        else          { mbar_wait_(mb1, ph1); }

        const unsigned long long* A8 =
            (const unsigned long long*)(smf + (cur ? OFF_A1 : OFF_A0));
        const int rb0 = 101 * tx;
        const int rb1 = 101 * (tx + 32);

        unsigned long long acc2[2][5];
        #pragma unroll
        for (int i = 0; i < 2; i++)
            #pragma unroll
            for (int j = 0; j < 5; j++) acc2[i][j] = 0ull;

        #pragma unroll 3
        for (int kk = 0; kk < 51; kk++) {
            unsigned long long a00 = A8[rb0 + 2 * kk];
            unsigned long long a01 = A8[rb0 + 2 * kk + 1];
            unsigned long long a10 = A8[rb1 + 2 * kk];
            unsigned long long a11 = A8[rb1 + 2 * kk + 1];
            ulonglong2 b[5];
            #pragma unroll
            for (int j = 0; j < 5; j++) b[j] = B2[(w + 20 * j) * 51 + kk];
            #pragma unroll
            for (int j = 0; j < 5; j++) {
                acc2[0][j] = ffma2_(a00, b[j].x, acc2[0][j]);
                acc2[0][j] = ffma2_(a01, b[j].y, acc2[0][j]);
                acc2[1][j] = ffma2_(a10, b[j].x, acc2[1][j]);
                acc2[1][j] = ffma2_(a11, b[j].y, acc2[1][j]);
            }
        }
        if (cur == 0) ph0 ^= 1; else ph1 ^= 1;

        #pragma unroll
        for (int j = 0; j < 5; j++) {
            int c = w + 20 * j;
            ep[tx * 101 + c]        = lo_(acc2[0][j]) + hi_(acc2[0][j]) + bias_j[j];
            ep[(tx + 32) * 101 + c] = lo_(acc2[1][j]) + hi_(acc2[1][j]) + bias_j[j];
        }
        __syncthreads();
        {
            float* gout = g_xp + (size_t)(mt * 64) * N2_ + dir * H_;
            #pragma unroll
            for (int q = 0; q < 10; q++) {
                int e = tid + q * PJ_T;
                int r = e / 100, c = e - r * 100;
                gout[(size_t)r * N2_ + c] = ep[r * 101 + c];
            }
        }
        __syncthreads();
        cur ^= 1;
    }
}

// =====================================================================
// Kernel 2: recurrent scans (proven R7 version, frozen).
// =====================================================================
__global__ __launch_bounds__(128) void rnn_kernel(
    const float* __restrict__ Whhf, const float* __restrict__ Whhb)
{
    const int chain = blockIdx.x;        // 0..255
    const int dir   = chain >> 7;        // 0 fwd, 1 bwd
    const int b     = chain & 127;
    const int j     = threadIdx.x;       // 0..127
    const int jc    = (j < H_) ? j : (H_ - 1);
    const int act   = (j < H_) ? 1 : 0;

    __shared__ __align__(16) float hs[2][104];

    const float* Whh = dir ? Whhb : Whhf;
    unsigned long long w2[50];
    {
        const ulonglong2* wp = (const ulonglong2*)(Whh + jc * H_);
        #pragma unroll
        for (int k = 0; k < 25; k++) { ulonglong2 t = wp[k]; w2[2*k] = t.x; w2[2*k+1] = t.y; }
    }
    if (j < 104) { hs[0][j] = 0.f; hs[1][j] = 0.f; }

    // desync co-resident CTAs so their stall phases interleave
    if (chain & 1) __nanosleep(150);
    __syncthreads();

    const unsigned hs_base = smem_u32_(&hs[0][0]);
    const float* xpb = g_xp + (size_t)b * N2_ + dir * H_ + jc;
    float*       hgb = g_h  + (size_t)b * N2_ + dir * H_ + jc;
    const int s0 = dir ? (S_ - 1) : 0;
    const int ds = dir ? -1 : 1;
    const int STRIDE = B_ * N2_;  // 25600

    float xq[4];
    #pragma unroll
    for (int q = 0; q < 4; q++) xq[q] = xpb[(size_t)(s0 + ds * q) * STRIDE];

    int p = 0;
    #pragma unroll 4
    for (int t = 0; t < S_; t++) {
        const int s = s0 + ds * t;
        const float x0 = xq[t & 3];
        int tp = t + 4; tp = (tp < S_) ? tp : (S_ - 1);     // clamp, branch-free
        xq[t & 3] = xpb[(size_t)(s0 + ds * tp) * STRIDE];

        unsigned long long a[8];
        a[0] = pack2_(x0, 0.f);
        #pragma unroll
        for (int q = 1; q < 8; q++) a[q] = 0ull;

        const ulonglong2* hv2 = (const ulonglong2*)hs[p];
        #pragma unroll
        for (int k = 0; k < 25; k++) {
            ulonglong2 h2 = hv2[k];
            a[(2*k)     & 7] = ffma2_(w2[2*k],     h2.x, a[(2*k)     & 7]);
            a[(2*k + 1) & 7] = ffma2_(w2[2*k + 1], h2.y, a[(2*k + 1) & 7]);
        }
        unsigned long long r0 = addf2_(addf2_(a[0], a[4]), addf2_(a[1], a[5]));
        unsigned long long r1 = addf2_(addf2_(a[2], a[6]), addf2_(a[3], a[7]));
        unsigned long long rr = addf2_(r0, r1);
        float acc = lo_(rr) + hi_(rr);

        // tanh(x) = 1 - 2/(e^{2x}+1); inf-safe, ~1e-7 abs err
        float e2 = __expf(acc + acc);
        float hn = 1.f - __fdividef(2.f, e2 + 1.f);

        sts_pred_(act, hs_base + (unsigned)((p ^ 1) * 104 + j) * 4u, hn);
        stg_pred_(act, hgb + (size_t)s * STRIDE, hn);
        __syncthreads();
        p ^= 1;
    }
}

// =====================================================================
// Kernel 3: logits + softmax -> emissions. Thread per (s,b) row.
// =====================================================================
__global__ __launch_bounds__(256) void logits_kernel(
    const float* __restrict__ Wout, const float* __restrict__ bout)
{
    __shared__ __align__(16) float wt[N2_ * 20];   // W_out^T, K padded 19->20
    const int tid = threadIdx.x;
    for (int e = tid; e < N2_ * 20; e += 256) {
        int f = e / 20, k = e - f * 20;
        wt[e] = (k < K_) ? Wout[k * N2_ + f] : 0.f;
    }
    __syncthreads();

    const int m = blockIdx.x * 256 + tid;
    const float4* hp = (const float4*)(g_h + (size_t)m * N2_);
    const ulonglong2* wt2 = (const ulonglong2*)wt;

    unsigned long long acc2[10];
    #pragma unroll
    for (int q = 0; q < 10; q++) acc2[q] = 0ull;

    for (int f4 = 0; f4 < 50; f4++) {
        float4 hv = __ldg(&hp[f4]);
        float hh[4] = {hv.x, hv.y, hv.z, hv.w};
        #pragma unroll
        for (int cc = 0; cc < 4; cc++) {
            const int f = f4 * 4 + cc;
            const unsigned long long hb = pack2_(hh[cc], hh[cc]);
            #pragma unroll
            for (int q = 0; q < 5; q++) {
                ulonglong2 wv = wt2[f * 5 + q];
                acc2[2*q]     = ffma2_(hb, wv.x, acc2[2*q]);
                acc2[2*q + 1] = ffma2_(hb, wv.y, acc2[2*q + 1]);
            }
        }
    }

    float acc[20];
    #pragma unroll
    for (int q = 0; q < 10; q++) { acc[2*q] = lo_(acc2[q]); acc[2*q+1] = hi_(acc2[q]); }

    float mx = -1e30f;
    #pragma unroll
    for (int k = 0; k < K_; k++) { acc[k] += __ldg(&bout[k]); mx = fmaxf(mx, acc[k]); }
    float sum = 0.f;
    #pragma unroll
    for (int k = 0; k < K_; k++) { acc[k] = __expf(acc[k] - mx); sum += acc[k]; }
    const float inv = 1.f / sum;
    float* e = g_em + (size_t)m * K_;
    #pragma unroll
    for (int k = 0; k < K_; k++) e[k] = acc[k] * inv;
}

// =====================================================================
// Kernel 4: Viterbi decode. Warp per sequence; smem score exchange.
//   SPILL-FREE inner loop: running argmax (no bv/bi/s arrays) -- each
//   float4 of scores consumed immediately; live set ~35 regs. Strict >
//   keeps the first (lowest-index) max == jnp.argmax semantics.
//   256 CTAs x 4 warps spreads warps over all SMs.
// =====================================================================
#define VB_W 4
__global__ __launch_bounds__(128) void viterbi_kernel(
    const float* __restrict__ start, const float* __restrict__ endt,
    const float* __restrict__ trans, float* __restrict__ out)
{
    __shared__ unsigned char hist[VB_W][127][20];
    __shared__ __align__(16) float sc[VB_W][2][20];
    const int w    = threadIdx.x >> 5;
    const int lane = threadIdx.x & 31;
    const int n    = blockIdx.x * VB_W + w;    // sequence 0..1023
    const int j    = lane;
    const bool act = (j < K_);

    float tr[K_];
    #pragma unroll
    for (int i = 0; i < K_; i++) tr[i] = act ? trans[i * K_ + j] : 0.f;

    const float* emn = g_em + (size_t)n * B_ * K_;
    float score = act ? (start[j] + emn[j]) : -1e30f;
    if (act) sc[w][0][j] = score;
    if (lane == 19) sc[w][0][19] = -1e30f;   // pad slot (never used as source)
    __syncwarp();

    int p = 0;
    for (int t = 1; t < B_; t++) {
        const float e = act ? emn[t * K_ + j] : 0.f;

        float best; int bidx;
        // consume each score immediately after load: no arrays, no spills
        #define VSTEP(SV, I) do { \
            float vv_ = (SV) + tr[I]; \
            bool  tk_ = (vv_ > best); \
            best = tk_ ? vv_ : best; \
            bidx = tk_ ? (I) : bidx; } while (0)

        {
            float4 s0 = *(const float4*)&sc[w][p][0];
            best = s0.x + tr[0]; bidx = 0;
            VSTEP(s0.y, 1); VSTEP(s0.z, 2); VSTEP(s0.w, 3);
        }
        {
            float4 s1 = *(const float4*)&sc[w][p][4];
            VSTEP(s1.x, 4); VSTEP(s1.y, 5); VSTEP(s1.z, 6); VSTEP(s1.w, 7);
        }
        {
            float4 s2 = *(const float4*)&sc[w][p][8];
            VSTEP(s2.x, 8); VSTEP(s2.y, 9); VSTEP(s2.z, 10); VSTEP(s2.w, 11);
        }
        {
            float4 s3 = *(const float4*)&sc[w][p][12];
            VSTEP(s3.x, 12); VSTEP(s3.y, 13); VSTEP(s3.z, 14); VSTEP(s3.w, 15);
        }
        {
            float4 s4 = *(const float4*)&sc[w][p][16];
            VSTEP(s4.x, 16); VSTEP(s4.y, 17); VSTEP(s4.z, 18);
        }
        #undef VSTEP

        if (act) hist[w][t - 1][j] = (unsigned char)bidx;
        score = best + e;
        if (act) sc[w][p ^ 1][j] = score;
        __syncwarp();
        p ^= 1;
    }

    float v  = act ? (score + endt[j]) : -1e30f;
    int  idx = j;
    #pragma unroll
    for (int off = 16; off; off >>= 1) {
        float ov = __shfl_down_sync(0xffffffffu, v, off);
        int   oi = __shfl_down_sync(0xffffffffu, idx, off);
        if (ov > v || (ov == v && oi < idx)) { v = ov; idx = oi; }
    }
    __syncwarp();

    if (lane == 0) {
        int tag = idx;
        float* o = out + (size_t)n * B_;
        o[B_ - 1] = (float)tag;
        for (int t = B_ - 2; t >= 0; t--) {
            tag  = hist[w][t][tag];
            o[t] = (float)tag;
        }
    }
}

// =====================================================================
extern "C" void kernel_launch(void* const* d_in, const int* in_sizes, int n_in,
                              void* d_out, int out_size)
{
    const float* x     = (const float*)d_in[0];
    const float* Wihf  = (const float*)d_in[1];
    const float* Whhf  = (const float*)d_in[2];
    const float* bihf  = (const float*)d_in[3];
    const float* bhhf  = (const float*)d_in[4];
    const float* Wihb  = (const float*)d_in[5];
    const float* Whhb  = (const float*)d_in[6];
    const float* bihb  = (const float*)d_in[7];
    const float* bhhb  = (const float*)d_in[8];
    const float* Wout  = (const float*)d_in[9];
    const float* bout  = (const float*)d_in[10];
    const float* start = (const float*)d_in[11];
    const float* endt  = (const float*)d_in[12];
    const float* trans = (const float*)d_in[13];
    float* out = (float*)d_out;

    cudaFuncSetAttribute(proj_kernel, cudaFuncAttributeMaxDynamicSharedMemorySize, PJ_SMEM);

    // no spacers: viterbi is the 4th app launch (ncu capture slot)
    proj_kernel<<<PG_G, PJ_T, PJ_SMEM>>>(x, Wihf, Wihb, bihf, bhhf, bihb, bhhb);
    rnn_kernel<<<2 * B_, 128>>>(Whhf, Whhb);
    logits_kernel<<<(S_ * B_) / 256, 256>>>(Wout, bout);
    viterbi_kernel<<<S_ / VB_W, 128>>>(start, endt, trans, out);
}

// round 16
// speedup vs baseline: 1.1045x; 1.0155x over previous
#include <cuda_runtime.h>
#include <math.h>

#define S_  1024
#define B_  128
#define F_  202
#define H_  100
#define K_  19
#define N2_ 200   // 2*H

// ---- scratch (device globals: no runtime allocation allowed) ----
__device__ float g_xp[(size_t)S_ * B_ * N2_];  // input projections, both dirs
__device__ float g_h [(size_t)S_ * B_ * N2_];  // hidden states [hf | hb]
__device__ float g_em[(size_t)S_ * B_ * K_];   // softmax emissions

// ---- packed dual-fp32 helpers (sm_103a f32x2 pipe) ----
static __device__ __forceinline__ unsigned long long ffma2_(
    unsigned long long a, unsigned long long b, unsigned long long c)
{
    unsigned long long d;
    asm("fma.rn.f32x2 %0, %1, %2, %3;" : "=l"(d) : "l"(a), "l"(b), "l"(c));
    return d;
}
static __device__ __forceinline__ unsigned long long addf2_(
    unsigned long long a, unsigned long long b)
{
    unsigned long long d;
    asm("add.rn.f32x2 %0, %1, %2;" : "=l"(d) : "l"(a), "l"(b));
    return d;
}
static __device__ __forceinline__ float lo_(unsigned long long v) {
    return __uint_as_float((unsigned)(v & 0xffffffffull));
}
static __device__ __forceinline__ float hi_(unsigned long long v) {
    return __uint_as_float((unsigned)(v >> 32));
}
static __device__ __forceinline__ unsigned long long pack2_(float lo, float hi) {
    unsigned long long r;
    asm("mov.b64 %0, {%1, %2};" : "=l"(r) : "f"(lo), "f"(hi));
    return r;
}
// predicated stores (single @p instruction, no BSSY/BSYNC envelope)
static __device__ __forceinline__ void sts_pred_(int pred, unsigned addr, float v) {
    asm volatile("{ .reg .pred p; setp.ne.s32 p, %0, 0; @p st.shared.f32 [%1], %2; }"
                 :: "r"(pred), "r"(addr), "f"(v));
}
static __device__ __forceinline__ void stg_pred_(int pred, float* ptr, float v) {
    asm volatile("{ .reg .pred p; setp.ne.s32 p, %0, 0; @p st.global.f32 [%1], %2; }"
                 :: "r"(pred), "l"(ptr), "f"(v));
}
static __device__ __forceinline__ unsigned smem_u32_(const void* p) {
    unsigned a;
    asm("{ .reg .u64 t; cvta.to.shared.u64 t, %1; cvt.u32.u64 %0, t; }" : "=r"(a) : "l"(p));
    return a;
}
// ---- mbarrier + 1D bulk-async copy (UBLKCP) ----
static __device__ __forceinline__ void mbar_init_(unsigned mbar, int cnt) {
    asm volatile("mbarrier.init.shared.b64 [%0], %1;" :: "r"(mbar), "r"(cnt) : "memory");
}
static __device__ __forceinline__ void mbar_expect_(unsigned mbar, unsigned bytes) {
    asm volatile("mbarrier.arrive.expect_tx.shared.b64 _, [%0], %1;"
                 :: "r"(mbar), "r"(bytes) : "memory");
}
static __device__ __forceinline__ void bulk_g2s_(unsigned dst, const void* src,
                                                 unsigned bytes, unsigned mbar) {
    asm volatile("cp.async.bulk.shared::cta.global.mbarrier::complete_tx::bytes "
                 "[%0], [%1], %2, [%3];"
                 :: "r"(dst), "l"(src), "r"(bytes), "r"(mbar) : "memory");
}
static __device__ __forceinline__ void mbar_wait_(unsigned mbar, unsigned phase) {
    unsigned done;
    asm volatile(
        "{\n\t.reg .pred p;\n\t"
        "mbarrier.try_wait.parity.acquire.cta.shared::cta.b64 p, [%1], %2;\n\t"
        "selp.b32 %0, 1, 0, p;\n\t}"
        : "=r"(done) : "r"(mbar), "r"(phase) : "memory");
    if (!done) {
        asm volatile(
            "{\n\t.reg .pred P1;\n\t"
            "WL_%=:\n\t"
            "mbarrier.try_wait.parity.acquire.cta.shared::cta.b64 P1, [%0], %1, 0x989680;\n\t"
            "@P1 bra.uni WD_%=;\n\t"
            "bra.uni WL_%=;\n\t"
            "WD_%=:\n\t}"
            :: "r"(mbar), "r"(phase) : "memory");
    }
}

// profiling-slot spacer (ncu captures the 4th app launch; make it rnn)
__global__ void noop_kernel() {}

// =====================================================================
// Kernel 1: persistent input projection (proven R10 config, unchanged).
// =====================================================================
#define PG_DIR  74
#define PG_G    148
#define PJ_T    640
#define TILE_BYTES 51712u                 // 64*202*4
#define OFF_A0  0
#define OFF_A1  12936
#define OFF_B   25872                     // 100*204
#define OFF_EP  46272                     // 64*101
#define OFF_MB  52736
#define PJ_SMEM ((OFF_MB + 8) * 4)        // 210976 bytes
#define NTILES  2048

__global__ __launch_bounds__(PJ_T, 1) void proj_kernel(
    const float* __restrict__ x,
    const float* __restrict__ Wf, const float* __restrict__ Wb,
    const float* __restrict__ bihf, const float* __restrict__ bhhf,
    const float* __restrict__ bihb, const float* __restrict__ bhhb)
{
    extern __shared__ __align__(16) float smf[];
    const int tid = threadIdx.x;
    const int dir = (blockIdx.x >= PG_DIR) ? 1 : 0;
    const int cid = blockIdx.x - dir * PG_DIR;   // 0..73
    const float* W   = dir ? Wb   : Wf;
    const float* bih = dir ? bihb : bihf;
    const float* bhh = dir ? bhhb : bhhf;

    const unsigned mb0 = smem_u32_(smf + OFF_MB);
    const unsigned mb1 = mb0 + 8;
    const unsigned ab0 = smem_u32_(smf + OFF_A0);
    const unsigned ab1 = smem_u32_(smf + OFF_A1);

    if (tid == 0) { mbar_init_(mb0, 1); mbar_init_(mb1, 1); }
    if (tid < 8)       smf[OFF_A0 + 12928 + tid] = 0.f;
    else if (tid < 16) smf[OFF_A1 + 12928 + (tid - 8)] = 0.f;

    for (int e = tid; e < 100 * 204; e += PJ_T) {
        int n = e / 204, f = e - n * 204;
        smf[OFF_B + e] = (f < F_) ? W[n * F_ + f] : 0.f;
    }
    __syncthreads();

    if (tid == 0) {
        mbar_expect_(mb0, TILE_BYTES);
        bulk_g2s_(ab0, x + (size_t)cid * 12928, TILE_BYTES, mb0);
    }

    const int tx = tid & 31;
    const int w  = tid >> 5;
    float bias_j[5];
    #pragma unroll
    for (int j = 0; j < 5; j++) { int c = w + 20 * j; bias_j[j] = bih[c] + bhh[c]; }

    const ulonglong2* B2 = (const ulonglong2*)(smf + OFF_B);
    float* ep = smf + OFF_EP;

    int cur = 0;
    unsigned ph0 = 0, ph1 = 0;
    for (int mt = cid; mt < NTILES; mt += PG_DIR) {
        int nt = mt + PG_DIR;
        if (tid == 0 && nt < NTILES) {
            unsigned mbn = cur ? mb0 : mb1;
            unsigned abn = cur ? ab0 : ab1;
            mbar_expect_(mbn, TILE_BYTES);
            bulk_g2s_(abn, x + (size_t)nt * 12928, TILE_BYTES, mbn);
        }
        if (cur == 0) { mbar_wait_(mb0, ph0); }
        else          { mbar_wait_(mb1, ph1); }

        const unsigned long long* A8 =
            (const unsigned long long*)(smf + (cur ? OFF_A1 : OFF_A0));
        const int rb0 = 101 * tx;
        const int rb1 = 101 * (tx + 32);

        unsigned long long acc2[2][5];
        #pragma unroll
        for (int i = 0; i < 2; i++)
            #pragma unroll
            for (int j = 0; j < 5; j++) acc2[i][j] = 0ull;

        #pragma unroll 3
        for (int kk = 0; kk < 51; kk++) {
            unsigned long long a00 = A8[rb0 + 2 * kk];
            unsigned long long a01 = A8[rb0 + 2 * kk + 1];
            unsigned long long a10 = A8[rb1 + 2 * kk];
            unsigned long long a11 = A8[rb1 + 2 * kk + 1];
            ulonglong2 b[5];
            #pragma unroll
            for (int j = 0; j < 5; j++) b[j] = B2[(w + 20 * j) * 51 + kk];
            #pragma unroll
            for (int j = 0; j < 5; j++) {
                acc2[0][j] = ffma2_(a00, b[j].x, acc2[0][j]);
                acc2[0][j] = ffma2_(a01, b[j].y, acc2[0][j]);
                acc2[1][j] = ffma2_(a10, b[j].x, acc2[1][j]);
                acc2[1][j] = ffma2_(a11, b[j].y, acc2[1][j]);
            }
        }
        if (cur == 0) ph0 ^= 1; else ph1 ^= 1;

        #pragma unroll
        for (int j = 0; j < 5; j++) {
            int c = w + 20 * j;
            ep[tx * 101 + c]        = lo_(acc2[0][j]) + hi_(acc2[0][j]) + bias_j[j];
            ep[(tx + 32) * 101 + c] = lo_(acc2[1][j]) + hi_(acc2[1][j]) + bias_j[j];
        }
        __syncthreads();
        {
            float* gout = g_xp + (size_t)(mt * 64) * N2_ + dir * H_;
            #pragma unroll
            for (int q = 0; q < 10; q++) {
                int e = tid + q * PJ_T;
                int r = e / 100, c = e - r * 100;
                gout[(size_t)r * N2_ + c] = ep[r * 101 + c];
            }
        }
        __syncthreads();
        cur ^= 1;
    }
}

// =====================================================================
// Kernel 2: recurrent scans (R7 body). NEW: desync keyed on dir --
//   co-resident CTA pairs are (c, c+148) = (dir0, dir1), so offsetting
//   dir1 by ~half a step interleaves the pair's FMA/stall phases.
// =====================================================================
__global__ __launch_bounds__(128) void rnn_kernel(
    const float* __restrict__ Whhf, const float* __restrict__ Whhb)
{
    const int chain = blockIdx.x;        // 0..255
    const int dir   = chain >> 7;        // 0 fwd, 1 bwd
    const int b     = chain & 127;
    const int j     = threadIdx.x;       // 0..127
    const int jc    = (j < H_) ? j : (H_ - 1);
    const int act   = (j < H_) ? 1 : 0;

    __shared__ __align__(16) float hs[2][104];

    const float* Whh = dir ? Whhb : Whhf;
    unsigned long long w2[50];
    {
        const ulonglong2* wp = (const ulonglong2*)(Whh + jc * H_);
        #pragma unroll
        for (int k = 0; k < 25; k++) { ulonglong2 t = wp[k]; w2[2*k] = t.x; w2[2*k+1] = t.y; }
    }
    if (j < 104) { hs[0][j] = 0.f; hs[1][j] = 0.f; }

    // desync co-resident (dir0, dir1) CTA pairs by ~half a step
    if (dir) __nanosleep(200);
    __syncthreads();

    const unsigned hs_base = smem_u32_(&hs[0][0]);
    const float* xpb = g_xp + (size_t)b * N2_ + dir * H_ + jc;
    float*       hgb = g_h  + (size_t)b * N2_ + dir * H_ + jc;
    const int s0 = dir ? (S_ - 1) : 0;
    const int ds = dir ? -1 : 1;
    const int STRIDE = B_ * N2_;  // 25600

    float xq[4];
    #pragma unroll
    for (int q = 0; q < 4; q++) xq[q] = xpb[(size_t)(s0 + ds * q) * STRIDE];

    int p = 0;
    #pragma unroll 4
    for (int t = 0; t < S_; t++) {
        const int s = s0 + ds * t;
        const float x0 = xq[t & 3];
        int tp = t + 4; tp = (tp < S_) ? tp : (S_ - 1);     // clamp, branch-free
        xq[t & 3] = xpb[(size_t)(s0 + ds * tp) * STRIDE];

        unsigned long long a[8];
        a[0] = pack2_(x0, 0.f);
        #pragma unroll
        for (int q = 1; q < 8; q++) a[q] = 0ull;

        const ulonglong2* hv2 = (const ulonglong2*)hs[p];
        #pragma unroll
        for (int k = 0; k < 25; k++) {
            ulonglong2 h2 = hv2[k];
            a[(2*k)     & 7] = ffma2_(w2[2*k],     h2.x, a[(2*k)     & 7]);
            a[(2*k + 1) & 7] = ffma2_(w2[2*k + 1], h2.y, a[(2*k + 1) & 7]);
        }
        unsigned long long r0 = addf2_(addf2_(a[0], a[4]), addf2_(a[1], a[5]));
        unsigned long long r1 = addf2_(addf2_(a[2], a[6]), addf2_(a[3], a[7]));
        unsigned long long rr = addf2_(r0, r1);
        float acc = lo_(rr) + hi_(rr);

        // tanh(x) = 1 - 2/(e^{2x}+1); inf-safe, ~1e-7 abs err
        float e2 = __expf(acc + acc);
        float hn = 1.f - __fdividef(2.f, e2 + 1.f);

        sts_pred_(act, hs_base + (unsigned)((p ^ 1) * 104 + j) * 4u, hn);
        stg_pred_(act, hgb + (size_t)s * STRIDE, hn);
        __syncthreads();
        p ^= 1;
    }
}

// =====================================================================
// Kernel 3: logits + softmax -> emissions. Thread per (s,b) row.
// =====================================================================
__global__ __launch_bounds__(256) void logits_kernel(
    const float* __restrict__ Wout, const float* __restrict__ bout)
{
    __shared__ __align__(16) float wt[N2_ * 20];   // W_out^T, K padded 19->20
    const int tid = threadIdx.x;
    for (int e = tid; e < N2_ * 20; e += 256) {
        int f = e / 20, k = e - f * 20;
        wt[e] = (k < K_) ? Wout[k * N2_ + f] : 0.f;
    }
    __syncthreads();

    const int m = blockIdx.x * 256 + tid;
    const float4* hp = (const float4*)(g_h + (size_t)m * N2_);
    const ulonglong2* wt2 = (const ulonglong2*)wt;

    unsigned long long acc2[10];
    #pragma unroll
    for (int q = 0; q < 10; q++) acc2[q] = 0ull;

    for (int f4 = 0; f4 < 50; f4++) {
        float4 hv = __ldg(&hp[f4]);
        float hh[4] = {hv.x, hv.y, hv.z, hv.w};
        #pragma unroll
        for (int cc = 0; cc < 4; cc++) {
            const int f = f4 * 4 + cc;
            const unsigned long long hb = pack2_(hh[cc], hh[cc]);
            #pragma unroll
            for (int q = 0; q < 5; q++) {
                ulonglong2 wv = wt2[f * 5 + q];
                acc2[2*q]     = ffma2_(hb, wv.x, acc2[2*q]);
                acc2[2*q + 1] = ffma2_(hb, wv.y, acc2[2*q + 1]);
            }
        }
    }

    float acc[20];
    #pragma unroll
    for (int q = 0; q < 10; q++) { acc[2*q] = lo_(acc2[q]); acc[2*q+1] = hi_(acc2[q]); }

    float mx = -1e30f;
    #pragma unroll
    for (int k = 0; k < K_; k++) { acc[k] += __ldg(&bout[k]); mx = fmaxf(mx, acc[k]); }
    float sum = 0.f;
    #pragma unroll
    for (int k = 0; k < K_; k++) { acc[k] = __expf(acc[k] - mx); sum += acc[k]; }
    const float inv = 1.f / sum;
    float* e = g_em + (size_t)m * K_;
    #pragma unroll
    for (int k = 0; k < K_; k++) e[k] = acc[k] * inv;
}

// =====================================================================
// Kernel 4: Viterbi decode (reverted to proven R12 version: smem score
//   exchange + depth-5 tie-stable tree argmax).
// =====================================================================
__global__ __launch_bounds__(256) void viterbi_kernel(
    const float* __restrict__ start, const float* __restrict__ endt,
    const float* __restrict__ trans, float* __restrict__ out)
{
    __shared__ unsigned char hist[8][127][20];
    __shared__ __align__(16) float sc[8][2][20];
    const int w    = threadIdx.x >> 5;
    const int lane = threadIdx.x & 31;
    const int n    = blockIdx.x * 8 + w;
    const int j    = lane;
    const bool act = (j < K_);

    float tr[K_];
    #pragma unroll
    for (int i = 0; i < K_; i++) tr[i] = act ? trans[i * K_ + j] : 0.f;

    const float* emn = g_em + (size_t)n * B_ * K_;
    float score = act ? (start[j] + emn[j]) : -1e30f;
    if (act) sc[w][0][j] = score;
    if (lane == 19) sc[w][0][19] = -1e30f;
    __syncwarp();

    int p = 0;
    for (int t = 1; t < B_; t++) {
        const float e = act ? emn[t * K_ + j] : 0.f;
        float4 s0 = *(const float4*)&sc[w][p][0];
        float4 s1 = *(const float4*)&sc[w][p][4];
        float4 s2 = *(const float4*)&sc[w][p][8];
        float4 s3 = *(const float4*)&sc[w][p][12];
        float4 s4 = *(const float4*)&sc[w][p][16];
        float s[20] = {s0.x,s0.y,s0.z,s0.w, s1.x,s1.y,s1.z,s1.w,
                       s2.x,s2.y,s2.z,s2.w, s3.x,s3.y,s3.z,s3.w,
                       s4.x,s4.y,s4.z,s4.w};
        float bv[K_]; int bi[K_];
        #pragma unroll
        for (int i = 0; i < K_; i++) { bv[i] = s[i] + tr[i]; bi[i] = i; }
        // tie-stable tree argmax: strict > keeps the LOWER index on ties
        #pragma unroll
        for (int st = 1; st < 32; st <<= 1)
            #pragma unroll
            for (int i = 0; i + st < K_; i += 2 * st) {
                bool take = (bv[i + st] > bv[i]);
                bv[i] = take ? bv[i + st] : bv[i];
                bi[i] = take ? bi[i + st] : bi[i];
            }
        if (act) hist[w][t - 1][j] = (unsigned char)bi[0];
        score = bv[0] + e;
        if (act) sc[w][p ^ 1][j] = score;
        __syncwarp();
        p ^= 1;
    }

    float v  = act ? (score + endt[j]) : -1e30f;
    int  idx = j;
    #pragma unroll
    for (int off = 16; off; off >>= 1) {
        float ov = __shfl_down_sync(0xffffffffu, v, off);
        int   oi = __shfl_down_sync(0xffffffffu, idx, off);
        if (ov > v || (ov == v && oi < idx)) { v = ov; idx = oi; }
    }
    __syncwarp();

    if (lane == 0) {
        int tag = idx;
        float* o = out + (size_t)n * B_;
        o[B_ - 1] = (float)tag;
        for (int t = B_ - 2; t >= 0; t--) {
            tag  = hist[w][t][tag];
            o[t] = (float)tag;
        }
    }
}

// =====================================================================
extern "C" void kernel_launch(void* const* d_in, const int* in_sizes, int n_in,
                              void* d_out, int out_size)
{
    const float* x     = (const float*)d_in[0];
    const float* Wihf  = (const float*)d_in[1];
    const float* Whhf  = (const float*)d_in[2];
    const float* bihf  = (const float*)d_in[3];
    const float* bhhf  = (const float*)d_in[4];
    const float* Wihb  = (const float*)d_in[5];
    const float* Whhb  = (const float*)d_in[6];
    const float* bihb  = (const float*)d_in[7];
    const float* bhhb  = (const float*)d_in[8];
    const float* Wout  = (const float*)d_in[9];
    const float* bout  = (const float*)d_in[10];
    const float* start = (const float*)d_in[11];
    const float* endt  = (const float*)d_in[12];
    const float* trans = (const float*)d_in[13];
    float* out = (float*)d_out;

    cudaFuncSetAttribute(proj_kernel, cudaFuncAttributeMaxDynamicSharedMemorySize, PJ_SMEM);

    // spacers: put rnn_kernel in the ncu capture slot (4th app launch)
    noop_kernel<<<1, 32>>>();
    noop_kernel<<<1, 32>>>();
    proj_kernel<<<PG_G, PJ_T, PJ_SMEM>>>(x, Wihf, Wihb, bihf, bhhf, bihb, bhhb);
    rnn_kernel<<<2 * B_, 128>>>(Whhf, Whhb);
    logits_kernel<<<(S_ * B_) / 256, 256>>>(Wout, bout);
    viterbi_kernel<<<S_ / 8, 256>>>(start, endt, trans, out);
}